// round 14
// baseline (speedup 1.0000x reference)
#include <cuda_runtime.h>
#include <cuda_fp16.h>
#include <math.h>

typedef unsigned int u32;

#define H 4096
#define IDIM 5632
#define NE 8
#define T 4096
#define NSLOTS (T * 2)
#define BM 128
#define BN 128
#define BK 64
#define ASTG 16384
#define BSTG 16384
#define SMEMSZ (1024 + 3 * ASTG + 2 * BSTG)

// ---------------- scratch (device globals; allocation-free) ----------------
__device__ __half g_hx[(size_t)T * H];
__device__ __half g_hact[(size_t)NSLOTS * IDIM];   // silu(g)*u, fp16
__device__ float  g_tmp[(size_t)NSLOTS * IDIM];    // raw gate values fp32
__device__ int    g_counts[NE];
__device__ int    g_offsets[NE];
__device__ int    g_cursor[NE];
__device__ int    g_topi[T * 2];
__device__ float  g_topw[T * 2];
__device__ int    g_tok[NSLOTS];
__device__ float  g_sw[NSLOTS];
__device__ float  g_psum[NE];
__device__ float  g_zsum;

// ---------------- helpers ----------------
__device__ __forceinline__ u32 smem_u32(const void* p) {
    u32 a;
    asm("{ .reg .u64 t; cvta.to.shared.u64 t, %1; cvt.u32.u64 %0, t; }" : "=r"(a) : "l"(p));
    return a;
}
// fp16 tile [128 rows][64 cols], 128B rows = 8 chunks of 16B, full XOR swizzle
__device__ __forceinline__ u32 swoff128(int row, int ch) {
    return (u32)(row * 128 + ((ch ^ (row & 7)) << 4));
}
__device__ __forceinline__ u32 packh(float lo, float hi) {
    u32 r;
    asm("cvt.rn.f16x2.f32 %0, %1, %2;" : "=r"(r) : "f"(hi), "f"(lo));
    return r;
}
// convert 8 fp32 -> 8 fp16 and store one 16B chunk
__device__ __forceinline__ void cvt_sts(u32 addr, float4 a, float4 b) {
    u32 h0 = packh(a.x, a.y), h1 = packh(a.z, a.w);
    u32 h2 = packh(b.x, b.y), h3 = packh(b.z, b.w);
    asm volatile("st.shared.v4.b32 [%0], {%1,%2,%3,%4};"
                 :: "r"(addr), "r"(h0), "r"(h1), "r"(h2), "r"(h3) : "memory");
}
#define CPASYNC(dst, src) \
    asm volatile("cp.async.cg.shared.global [%0], [%1], 16;" :: "r"(dst), "l"(src) : "memory")
#define CPCOMMIT() asm volatile("cp.async.commit_group;" ::: "memory")
#define CPWAIT1()  asm volatile("cp.async.wait_group 1;" ::: "memory")

#define LDSM4(R, A)                                                             \
    asm volatile("ldmatrix.sync.aligned.m8n8.x4.shared.b16 {%0,%1,%2,%3}, [%4];" \
        : "=r"((R)[0]), "=r"((R)[1]), "=r"((R)[2]), "=r"((R)[3]) : "r"(A))

__device__ __forceinline__ void mma16816(float* d, const u32* a, const u32* b) {
    asm volatile(
        "mma.sync.aligned.m16n8k16.row.col.f32.f16.f16.f32 "
        "{%0,%1,%2,%3},{%4,%5,%6,%7},{%8,%9},{%0,%1,%2,%3};"
        : "+f"(d[0]), "+f"(d[1]), "+f"(d[2]), "+f"(d[3])
        : "r"(a[0]), "r"(a[1]), "r"(a[2]), "r"(a[3]), "r"(b[0]), "r"(b[1]));
}

// ---------------- fp32 -> fp16 conversion pass (x only) ----------------
__global__ __launch_bounds__(256)
void cvt16(const float* __restrict__ s, __half* __restrict__ d, size_t n) {
    size_t i = ((size_t)blockIdx.x * 256 + threadIdx.x) * 8;
    if (i >= n) return;
    float4 v0 = *(const float4*)(s + i);
    float4 v1 = *(const float4*)(s + i + 4);
    uint4 o;
    o.x = packh(v0.x, v0.y); o.y = packh(v0.z, v0.w);
    o.z = packh(v1.x, v1.y); o.w = packh(v1.z, v1.w);
    *(uint4*)(d + i) = o;
}

// ---------------- small kernels ----------------
__global__ void reset_kernel() {
    int i = threadIdx.x;
    if (i < NE) { g_counts[i] = 0; g_cursor[i] = 0; g_psum[i] = 0.f; }
    if (i == 0) g_zsum = 0.f;
}

// router: 32 tokens/block, Wgate staged in 128KB smem, warp per 4 tokens
__global__ __launch_bounds__(256)
void router_kernel(const float* __restrict__ x, const float* __restrict__ Wgate) {
    extern __shared__ float swg[];   // NE*H fp32 = 128KB
    for (int i = threadIdx.x; i < NE * H / 4; i += 256)
        ((float4*)swg)[i] = ((const float4*)Wgate)[i];
    __syncthreads();

    int warp = threadIdx.x >> 5, lane = threadIdx.x & 31;
    int t0 = blockIdx.x * 32 + warp * 4;
    const float4* xr = (const float4*)(x + (size_t)t0 * H);
    const float4* wg4 = (const float4*)swg;

    float p[4][NE];
#pragma unroll
    for (int s = 0; s < 4; ++s)
#pragma unroll
        for (int e = 0; e < NE; ++e) p[s][e] = 0.f;

    for (int c = lane; c < H / 4; c += 32) {
        float4 wv[NE];
#pragma unroll
        for (int e = 0; e < NE; ++e) wv[e] = wg4[e * (H / 4) + c];
#pragma unroll
        for (int s = 0; s < 4; ++s) {
            float4 xv = xr[s * (H / 4) + c];
#pragma unroll
            for (int e = 0; e < NE; ++e)
                p[s][e] += xv.x * wv[e].x + xv.y * wv[e].y
                         + xv.z * wv[e].z + xv.w * wv[e].w;
        }
    }
#pragma unroll
    for (int s = 0; s < 4; ++s)
#pragma unroll
        for (int e = 0; e < NE; ++e)
#pragma unroll
            for (int o = 16; o; o >>= 1)
                p[s][e] += __shfl_xor_sync(~0u, p[s][e], o);

    if (lane < 4) {
        int s = lane;
        int t = t0 + s;
        float lg[NE];
#pragma unroll
        for (int e = 0; e < NE; ++e) lg[e] = p[s][e];
        float mx = lg[0];
#pragma unroll
        for (int e = 1; e < NE; ++e) mx = fmaxf(mx, lg[e]);
        float se = 0.f, pr[NE];
#pragma unroll
        for (int e = 0; e < NE; ++e) { pr[e] = expf(lg[e] - mx); se += pr[e]; }
        float inv = 1.f / se;
#pragma unroll
        for (int e = 0; e < NE; ++e) pr[e] *= inv;
        int i0 = 0;
#pragma unroll
        for (int e = 1; e < NE; ++e) if (pr[e] > pr[i0]) i0 = e;
        int i1 = (i0 == 0) ? 1 : 0;
#pragma unroll
        for (int e = 0; e < NE; ++e)
            if (e != i0 && pr[e] > pr[i1]) i1 = e;
        float w0 = pr[i0], w1 = pr[i1];
        float ws = 1.f / (w0 + w1);
        g_topi[2 * t] = i0;     g_topw[2 * t] = w0 * ws;
        g_topi[2 * t + 1] = i1; g_topw[2 * t + 1] = w1 * ws;
        atomicAdd(&g_counts[i0], 1);
        atomicAdd(&g_counts[i1], 1);
#pragma unroll
        for (int e = 0; e < NE; ++e) atomicAdd(&g_psum[e], pr[e]);
        float lse = mx + logf(se);
        atomicAdd(&g_zsum, lse * lse);
    }
}

__global__ void finalize_kernel(float* __restrict__ out, int out_size) {
    if (threadIdx.x == 0 && blockIdx.x == 0) {
        int off = 0;
        for (int e = 0; e < NE; ++e) { g_offsets[e] = off; g_cursor[e] = off; off += g_counts[e]; }
        float aux = 0.f;
        for (int e = 0; e < NE; ++e)
            aux += (g_psum[e] / (float)T) * ((float)g_counts[e] / (float)(T * 2));
        aux *= (float)NE;
        float z = g_zsum / (float)T;
        if (out_size > T * H) out[(size_t)T * H] = 0.02f * aux + 0.001f * z;
    }
}

__global__ void assign_kernel() {
    int t = blockIdx.x * blockDim.x + threadIdx.x;
    if (t >= T) return;
#pragma unroll
    for (int k = 0; k < 2; ++k) {
        int e = g_topi[2 * t + k];
        int s = atomicAdd(&g_cursor[e], 1);
        g_tok[s] = t;
        g_sw[s] = g_topw[2 * t + k];
    }
}

// ---------------- fp16 MMA GEMM; A fp16 cp.async 3-stage; B fp32 in-loop ----
// B conversion uses two half-loads (16 live regs max) to avoid R12's spills.
// MODE 0: A=hx(gather), B=Wg(fp32) -> g_tmp (raw gate, fp32)
// MODE 1: A=hx(gather), B=Wu(fp32) -> g_hact = silu(g_tmp)*u (fp16)
// MODE 2: A=g_hact,     B=Wd(fp32) -> out[tok] += w * result (atomic fp32)
template <int MODE>
__global__ __launch_bounds__(256, 2)
void gemm_kernel(const __half* __restrict__ Asrc, const float* __restrict__ W32,
                 float* __restrict__ outp) {
    constexpr int KD = (MODE == 2) ? IDIM : H;
    constexpr int KT = KD / BK;

    int e = blockIdx.z;
    int cnt = g_counts[e];
    int m0 = blockIdx.x * BM;
    if (m0 >= cnt) return;
    int base = g_offsets[e];
    int n0 = blockIdx.y * BN;

    extern __shared__ char smem[];
    const __half** aptr = (const __half**)smem;       // 128 row pointers (1 KB)
    u32 tilesA = smem_u32(smem) + 1024;               // 3 x 16KB
    u32 tilesB = tilesA + 3 * ASTG;                   // 2 x 16KB

    int tid = threadIdx.x, lane = tid & 31, wid = tid >> 5;
    int wm = wid & 3, wn = wid >> 2;

    if (tid < 128) {
        int r = m0 + tid;
        int slot = base + ((r < cnt) ? r : (cnt - 1));
        aptr[tid] = (MODE == 2) ? (Asrc + (size_t)slot * IDIM)
                                : (Asrc + (size_t)g_tok[slot] * H);
    }
    __syncthreads();

    const float* wB = W32 + (size_t)e * ((size_t)IDIM * H) + (size_t)n0 * KD;

    int lrow = tid >> 1, lch = (tid & 1) * 4;
    const __half* aRow = aptr[lrow] + lch * 8;
    const float* bRow = wB + (size_t)lrow * KD + lch * 8;
    u32 so0 = swoff128(lrow, lch),     so1 = swoff128(lrow, lch + 1);
    u32 so2 = swoff128(lrow, lch + 2), so3 = swoff128(lrow, lch + 3);

#define ISSUE_A(sb, k0) do {                  \
    u32 _s = (sb); int _k = (k0);             \
    CPASYNC(_s + so0, aRow + _k);             \
    CPASYNC(_s + so1, aRow + _k + 8);         \
    CPASYNC(_s + so2, aRow + _k + 16);        \
    CPASYNC(_s + so3, aRow + _k + 24);        \
} while (0)

    // prologue: A stages 0,1 via cp.async; B tile 0 converted directly
    ISSUE_A(tilesA, 0);
    CPCOMMIT();
    ISSUE_A(tilesA + ASTG, BK);
    CPCOMMIT();
    {
        float4 b0 = *(const float4*)(bRow);
        float4 b1 = *(const float4*)(bRow + 4);
        float4 b2 = *(const float4*)(bRow + 8);
        float4 b3 = *(const float4*)(bRow + 12);
        cvt_sts(tilesB + so0, b0, b1);
        cvt_sts(tilesB + so1, b2, b3);
        b0 = *(const float4*)(bRow + 16);
        b1 = *(const float4*)(bRow + 20);
        b2 = *(const float4*)(bRow + 24);
        b3 = *(const float4*)(bRow + 28);
        cvt_sts(tilesB + so2, b0, b1);
        cvt_sts(tilesB + so3, b2, b3);
    }

    float acc[2][8][4];
#pragma unroll
    for (int i = 0; i < 2; ++i)
#pragma unroll
        for (int j = 0; j < 8; ++j)
#pragma unroll
            for (int c = 0; c < 4; ++c) acc[i][j][c] = 0.f;

#pragma unroll 1
    for (int kt = 0; kt < KT; ++kt) {
        CPWAIT1();
        __syncthreads();
        if (kt + 2 < KT) ISSUE_A(tilesA + ((kt + 2) % 3) * ASTG, (kt + 2) * BK);
        CPCOMMIT();

        u32 sA = tilesA + (kt % 3) * ASTG;
        u32 sB = tilesB + (kt & 1) * BSTG;
        u32 nB = tilesB + ((kt + 1) & 1) * BSTG;
        bool pf = (kt + 1 < KT);
        const float* nb = bRow + (kt + 1) * BK;

        // first half of next B tile (16 regs, live until ks==1)
        float4 br0, br1, br2, br3;
        if (pf) {
            br0 = *(const float4*)(nb);
            br1 = *(const float4*)(nb + 4);
            br2 = *(const float4*)(nb + 8);
            br3 = *(const float4*)(nb + 12);
        }

#pragma unroll
        for (int ks = 0; ks < 4; ++ks) {
            u32 Ah[2][4];
#pragma unroll
            for (int mi = 0; mi < 2; ++mi) {
                int row = wm * 32 + mi * 16 + (lane & 15);
                int ch = ks * 2 + (lane >> 4);
                LDSM4(Ah[mi], sA + swoff128(row, ch));
            }
#pragma unroll
            for (int p = 0; p < 4; ++p) {
                int row = wn * 64 + p * 16 + ((lane >> 4) << 3) + (lane & 7);
                int ch = ks * 2 + ((lane >> 3) & 1);
                u32 Bh[4];
                LDSM4(Bh, sB + swoff128(row, ch));
#pragma unroll
                for (int mi = 0; mi < 2; ++mi) {
                    mma16816(acc[mi][2 * p],     Ah[mi], Bh);
                    mma16816(acc[mi][2 * p + 1], Ah[mi], Bh + 2);
                }
            }
            if (ks == 1 && pf) {
                cvt_sts(nB + so0, br0, br1);
                cvt_sts(nB + so1, br2, br3);
                br0 = *(const float4*)(nb + 16);
                br1 = *(const float4*)(nb + 20);
                br2 = *(const float4*)(nb + 24);
                br3 = *(const float4*)(nb + 28);
            }
            if (ks == 3 && pf) {
                cvt_sts(nB + so2, br0, br1);
                cvt_sts(nB + so3, br2, br3);
            }
        }
    }
#undef ISSUE_A

    // epilogue
    int rA = m0 + wm * 32 + (lane >> 2);
    int cA = n0 + wn * 64 + (lane & 3) * 2;
#pragma unroll
    for (int mi = 0; mi < 2; ++mi) {
#pragma unroll
        for (int ni = 0; ni < 8; ++ni) {
            int col = cA + ni * 8;
#pragma unroll
            for (int h = 0; h < 2; ++h) {
                int r = rA + mi * 16 + h * 8;
                if (r >= cnt) continue;
                float v0 = acc[mi][ni][2 * h], v1 = acc[mi][ni][2 * h + 1];
                int slot = base + r;
                if (MODE == 0) {
                    float2 o; o.x = v0; o.y = v1;
                    *(float2*)(g_tmp + (size_t)slot * IDIM + col) = o;
                } else if (MODE == 1) {
                    float2 g = *(const float2*)(g_tmp + (size_t)slot * IDIM + col);
                    float ax = g.x / (1.f + __expf(-g.x)) * v0;
                    float ay = g.y / (1.f + __expf(-g.y)) * v1;
                    *(u32*)(g_hact + (size_t)slot * IDIM + col) = packh(ax, ay);
                } else {
                    float w = g_sw[slot];
                    float* d = outp + (size_t)g_tok[slot] * H + col;
                    atomicAdd(d, w * v0);
                    atomicAdd(d + 1, w * v1);
                }
            }
        }
    }
}

// ---------------- launch ----------------
extern "C" void kernel_launch(void* const* d_in, const int* in_sizes, int n_in,
                              void* d_out, int out_size) {
    const float* x     = (const float*)d_in[0];
    const float* Wgate = (const float*)d_in[1];
    const float* Wg    = (const float*)d_in[2];
    const float* Wu    = (const float*)d_in[3];
    const float* Wd    = (const float*)d_in[4];
    float* out = (float*)d_out;

    cudaFuncSetAttribute(gemm_kernel<0>, cudaFuncAttributeMaxDynamicSharedMemorySize, SMEMSZ);
    cudaFuncSetAttribute(gemm_kernel<1>, cudaFuncAttributeMaxDynamicSharedMemorySize, SMEMSZ);
    cudaFuncSetAttribute(gemm_kernel<2>, cudaFuncAttributeMaxDynamicSharedMemorySize, SMEMSZ);
    cudaFuncSetAttribute(router_kernel, cudaFuncAttributeMaxDynamicSharedMemorySize,
                         NE * H * (int)sizeof(float));

    __half *hx, *hact;
    cudaGetSymbolAddress((void**)&hx, g_hx);
    cudaGetSymbolAddress((void**)&hact, g_hact);

    // one-time host-side resources (no device memory involved)
    static cudaStream_t s2 = 0;
    static cudaEvent_t evF = 0, evR = 0;
    if (!s2) {
        cudaStreamCreateWithFlags(&s2, cudaStreamNonBlocking);
        cudaEventCreateWithFlags(&evF, cudaEventDisableTiming);
        cudaEventCreateWithFlags(&evR, cudaEventDisableTiming);
    }

    cudaEventRecord(evF, 0);

    // s2: memset + router chain (independent of cvt_x)
    cudaStreamWaitEvent(s2, evF, 0);
    cudaMemsetAsync(out, 0, (size_t)out_size * sizeof(float), s2);
    reset_kernel<<<1, 32, 0, s2>>>();
    router_kernel<<<T / 32, 256, NE * H * sizeof(float), s2>>>(x, Wgate);
    finalize_kernel<<<1, 32, 0, s2>>>(out, out_size);
    assign_kernel<<<(T + 255) / 256, 256, 0, s2>>>();
    cudaEventRecord(evR, s2);

    // default: x fp32 -> fp16, then the GEMM chain (weights converted in-loop)
    cvt16<<<(u32)(((size_t)T * H) / 2048), 256>>>(x, hx, (size_t)T * H);
    cudaStreamWaitEvent(0, evR, 0);

    dim3 g1(T / BM, IDIM / BN, NE);   // (32, 44, 8)
    gemm_kernel<0><<<g1, 256, SMEMSZ>>>(hx, Wg, out);
    gemm_kernel<1><<<g1, 256, SMEMSZ>>>(hx, Wu, out);

    dim3 g2(T / BM, H / BN, NE);      // (32, 32, 8)
    gemm_kernel<2><<<g2, 256, SMEMSZ>>>(hact, Wd, out);
}

// round 15
// speedup vs baseline: 1.6504x; 1.6504x over previous
#include <cuda_runtime.h>
#include <cuda_fp16.h>
#include <math.h>

typedef unsigned int u32;

#define H 4096
#define IDIM 5632
#define NE 8
#define T 4096
#define NSLOTS (T * 2)
#define BM 128
#define BN 128
#define BK 64
// stage: A 16KB @0 | B 16KB @16384 => 32KB; 3 stages
#define STAGE 32768
#define SMEMSZ (1024 + 3 * STAGE)

// ---------------- scratch (device globals; allocation-free) ----------------
__device__ __half g_hx[(size_t)T * H];
__device__ __half g_hwg[(size_t)NE * IDIM * H];
__device__ __half g_hwu[(size_t)NE * IDIM * H];
__device__ __half g_hwd[(size_t)NE * H * IDIM];
__device__ __half g_hact[(size_t)NSLOTS * IDIM];   // silu(g)*u, fp16
__device__ __half g_htmp[(size_t)NSLOTS * IDIM];   // raw gate values fp16
__device__ int    g_counts[NE];
__device__ int    g_offsets[NE];
__device__ int    g_cursor[NE];
__device__ int    g_topi[T * 2];
__device__ float  g_topw[T * 2];
__device__ int    g_tok[NSLOTS];
__device__ float  g_sw[NSLOTS];
__device__ float  g_psum[NE];
__device__ float  g_zsum;

// ---------------- helpers ----------------
__device__ __forceinline__ u32 smem_u32(const void* p) {
    u32 a;
    asm("{ .reg .u64 t; cvta.to.shared.u64 t, %1; cvt.u32.u64 %0, t; }" : "=r"(a) : "l"(p));
    return a;
}
// fp16 tile [128 rows][64 cols], 128B rows = 8 chunks of 16B, full XOR swizzle
__device__ __forceinline__ u32 swoff128(int row, int ch) {
    return (u32)(row * 128 + ((ch ^ (row & 7)) << 4));
}
__device__ __forceinline__ u32 packh(float lo, float hi) {
    u32 r;
    asm("cvt.rn.f16x2.f32 %0, %1, %2;" : "=r"(r) : "f"(hi), "f"(lo));
    return r;
}
#define CPASYNC(dst, src) \
    asm volatile("cp.async.cg.shared.global [%0], [%1], 16;" :: "r"(dst), "l"(src) : "memory")
#define CPCOMMIT() asm volatile("cp.async.commit_group;" ::: "memory")
#define CPWAIT1()  asm volatile("cp.async.wait_group 1;" ::: "memory")

#define LDSM4(R, A)                                                             \
    asm volatile("ldmatrix.sync.aligned.m8n8.x4.shared.b16 {%0,%1,%2,%3}, [%4];" \
        : "=r"((R)[0]), "=r"((R)[1]), "=r"((R)[2]), "=r"((R)[3]) : "r"(A))

__device__ __forceinline__ void mma16816(float* d, const u32* a, const u32* b) {
    asm volatile(
        "mma.sync.aligned.m16n8k16.row.col.f32.f16.f16.f32 "
        "{%0,%1,%2,%3},{%4,%5,%6,%7},{%8,%9},{%0,%1,%2,%3};"
        : "+f"(d[0]), "+f"(d[1]), "+f"(d[2]), "+f"(d[3])
        : "r"(a[0]), "r"(a[1]), "r"(a[2]), "r"(a[3]), "r"(b[0]), "r"(b[1]));
}

// ---------------- fp32 -> fp16 conversion pass ----------------
__global__ __launch_bounds__(256)
void cvt16(const float* __restrict__ s, __half* __restrict__ d, size_t n) {
    size_t i = ((size_t)blockIdx.x * 256 + threadIdx.x) * 8;
    if (i >= n) return;
    float4 v0 = *(const float4*)(s + i);
    float4 v1 = *(const float4*)(s + i + 4);
    uint4 o;
    o.x = packh(v0.x, v0.y); o.y = packh(v0.z, v0.w);
    o.z = packh(v1.x, v1.y); o.w = packh(v1.z, v1.w);
    *(uint4*)(d + i) = o;
}

// ---------------- small kernels ----------------
__global__ void reset_kernel() {
    int i = threadIdx.x;
    if (i < NE) { g_counts[i] = 0; g_cursor[i] = 0; g_psum[i] = 0.f; }
    if (i == 0) g_zsum = 0.f;
}

// router: 32 tokens/block, Wgate staged in 128KB smem, warp per 4 tokens
__global__ __launch_bounds__(256)
void router_kernel(const float* __restrict__ x, const float* __restrict__ Wgate) {
    extern __shared__ float swg[];   // NE*H fp32 = 128KB
    for (int i = threadIdx.x; i < NE * H / 4; i += 256)
        ((float4*)swg)[i] = ((const float4*)Wgate)[i];
    __syncthreads();

    int warp = threadIdx.x >> 5, lane = threadIdx.x & 31;
    int t0 = blockIdx.x * 32 + warp * 4;
    const float4* xr = (const float4*)(x + (size_t)t0 * H);
    const float4* wg4 = (const float4*)swg;

    float p[4][NE];
#pragma unroll
    for (int s = 0; s < 4; ++s)
#pragma unroll
        for (int e = 0; e < NE; ++e) p[s][e] = 0.f;

    for (int c = lane; c < H / 4; c += 32) {
        float4 wv[NE];
#pragma unroll
        for (int e = 0; e < NE; ++e) wv[e] = wg4[e * (H / 4) + c];
#pragma unroll
        for (int s = 0; s < 4; ++s) {
            float4 xv = xr[s * (H / 4) + c];
#pragma unroll
            for (int e = 0; e < NE; ++e)
                p[s][e] += xv.x * wv[e].x + xv.y * wv[e].y
                         + xv.z * wv[e].z + xv.w * wv[e].w;
        }
    }
#pragma unroll
    for (int s = 0; s < 4; ++s)
#pragma unroll
        for (int e = 0; e < NE; ++e)
#pragma unroll
            for (int o = 16; o; o >>= 1)
                p[s][e] += __shfl_xor_sync(~0u, p[s][e], o);

    if (lane < 4) {
        int s = lane;
        int t = t0 + s;
        float lg[NE];
#pragma unroll
        for (int e = 0; e < NE; ++e) lg[e] = p[s][e];
        float mx = lg[0];
#pragma unroll
        for (int e = 1; e < NE; ++e) mx = fmaxf(mx, lg[e]);
        float se = 0.f, pr[NE];
#pragma unroll
        for (int e = 0; e < NE; ++e) { pr[e] = expf(lg[e] - mx); se += pr[e]; }
        float inv = 1.f / se;
#pragma unroll
        for (int e = 0; e < NE; ++e) pr[e] *= inv;
        int i0 = 0;
#pragma unroll
        for (int e = 1; e < NE; ++e) if (pr[e] > pr[i0]) i0 = e;
        int i1 = (i0 == 0) ? 1 : 0;
#pragma unroll
        for (int e = 0; e < NE; ++e)
            if (e != i0 && pr[e] > pr[i1]) i1 = e;
        float w0 = pr[i0], w1 = pr[i1];
        float ws = 1.f / (w0 + w1);
        g_topi[2 * t] = i0;     g_topw[2 * t] = w0 * ws;
        g_topi[2 * t + 1] = i1; g_topw[2 * t + 1] = w1 * ws;
        atomicAdd(&g_counts[i0], 1);
        atomicAdd(&g_counts[i1], 1);
#pragma unroll
        for (int e = 0; e < NE; ++e) atomicAdd(&g_psum[e], pr[e]);
        float lse = mx + logf(se);
        atomicAdd(&g_zsum, lse * lse);
    }
}

__global__ void finalize_kernel(float* __restrict__ out, int out_size) {
    if (threadIdx.x == 0 && blockIdx.x == 0) {
        int off = 0;
        for (int e = 0; e < NE; ++e) { g_offsets[e] = off; g_cursor[e] = off; off += g_counts[e]; }
        float aux = 0.f;
        for (int e = 0; e < NE; ++e)
            aux += (g_psum[e] / (float)T) * ((float)g_counts[e] / (float)(T * 2));
        aux *= (float)NE;
        float z = g_zsum / (float)T;
        if (out_size > T * H) out[(size_t)T * H] = 0.02f * aux + 0.001f * z;
    }
}

__global__ void assign_kernel() {
    int t = blockIdx.x * blockDim.x + threadIdx.x;
    if (t >= T) return;
#pragma unroll
    for (int k = 0; k < 2; ++k) {
        int e = g_topi[2 * t + k];
        int s = atomicAdd(&g_cursor[e], 1);
        g_tok[s] = t;
        g_sw[s] = g_topw[2 * t + k];
    }
}

// ---------------- fp16 MMA GEMM, cp.async 3-stage (R13-proven) -------------
// MODE 0: A=hx(gather), B=hwg -> g_htmp (raw gate, fp16)
// MODE 1: A=hx(gather), B=hwu -> g_hact = silu(g_htmp)*u (fp16)
// MODE 2: A=g_hact,     B=hwd -> out[tok] += w * result (atomic fp32)
template <int MODE>
__global__ __launch_bounds__(256, 2)
void gemm_kernel(const __half* __restrict__ Asrc, const __half* __restrict__ W,
                 float* __restrict__ outp) {
    constexpr int KD = (MODE == 2) ? IDIM : H;
    constexpr int KT = KD / BK;

    int e = blockIdx.z;
    int cnt = g_counts[e];
    int m0 = blockIdx.x * BM;
    if (m0 >= cnt) return;
    int base = g_offsets[e];
    int n0 = blockIdx.y * BN;

    extern __shared__ char smem[];
    const __half** aptr = (const __half**)smem;   // 128 row pointers (1 KB)
    u32 tiles = smem_u32(smem) + 1024;            // 3 stages x 32 KB

    int tid = threadIdx.x, lane = tid & 31, wid = tid >> 5;
    int wm = wid & 3, wn = wid >> 2;

    if (tid < 128) {
        int r = m0 + tid;
        int slot = base + ((r < cnt) ? r : (cnt - 1));
        aptr[tid] = (MODE == 2) ? (Asrc + (size_t)slot * IDIM)
                                : (Asrc + (size_t)g_tok[slot] * H);
    }
    __syncthreads();

    const __half* wB = W + (size_t)e * ((size_t)IDIM * H) + (size_t)n0 * KD;

    // loader: each thread copies 4 A chunks + 4 B chunks (16B each) per stage
    int lrow = tid >> 1, lch = (tid & 1) * 4;
    const __half* aRow = aptr[lrow] + lch * 8;
    const __half* bRow = wB + (size_t)lrow * KD + lch * 8;
    u32 so0 = swoff128(lrow, lch),     so1 = swoff128(lrow, lch + 1);
    u32 so2 = swoff128(lrow, lch + 2), so3 = swoff128(lrow, lch + 3);

#define ISSUE(sb, k0) do {                                  \
    u32 _s = (sb); int _k = (k0);                           \
    CPASYNC(_s + so0,         aRow + _k);                   \
    CPASYNC(_s + so1,         aRow + _k + 8);               \
    CPASYNC(_s + so2,         aRow + _k + 16);              \
    CPASYNC(_s + so3,         aRow + _k + 24);              \
    CPASYNC(_s + 16384 + so0, bRow + _k);                   \
    CPASYNC(_s + 16384 + so1, bRow + _k + 8);               \
    CPASYNC(_s + 16384 + so2, bRow + _k + 16);              \
    CPASYNC(_s + 16384 + so3, bRow + _k + 24);              \
} while (0)

    // prologue: stages 0 and 1
    ISSUE(tiles, 0);
    CPCOMMIT();
    ISSUE(tiles + STAGE, BK);
    CPCOMMIT();

    float acc[2][8][4];
#pragma unroll
    for (int i = 0; i < 2; ++i)
#pragma unroll
        for (int j = 0; j < 8; ++j)
#pragma unroll
            for (int c = 0; c < 4; ++c) acc[i][j][c] = 0.f;

#pragma unroll 1
    for (int kt = 0; kt < KT; ++kt) {
        CPWAIT1();
        __syncthreads();
        if (kt + 2 < KT) {
            int nslot = (kt + 2) % 3;
            ISSUE(tiles + nslot * STAGE, (kt + 2) * BK);
        }
        CPCOMMIT();

        u32 stage = tiles + (kt % 3) * STAGE;
#pragma unroll
        for (int ks = 0; ks < 4; ++ks) {
            u32 Ah[2][4];
#pragma unroll
            for (int mi = 0; mi < 2; ++mi) {
                int row = wm * 32 + mi * 16 + (lane & 15);
                int ch = ks * 2 + (lane >> 4);
                LDSM4(Ah[mi], stage + swoff128(row, ch));
            }
#pragma unroll
            for (int p = 0; p < 4; ++p) {
                int row = wn * 64 + p * 16 + ((lane >> 4) << 3) + (lane & 7);
                int ch = ks * 2 + ((lane >> 3) & 1);
                u32 Bh[4];
                LDSM4(Bh, stage + 16384 + swoff128(row, ch));
#pragma unroll
                for (int mi = 0; mi < 2; ++mi) {
                    mma16816(acc[mi][2 * p],     Ah[mi], Bh);
                    mma16816(acc[mi][2 * p + 1], Ah[mi], Bh + 2);
                }
            }
        }
    }
#undef ISSUE

    // epilogue
    int rA = m0 + wm * 32 + (lane >> 2);
    int cA = n0 + wn * 64 + (lane & 3) * 2;
#pragma unroll
    for (int mi = 0; mi < 2; ++mi) {
#pragma unroll
        for (int ni = 0; ni < 8; ++ni) {
            int col = cA + ni * 8;
#pragma unroll
            for (int h = 0; h < 2; ++h) {
                int r = rA + mi * 16 + h * 8;
                if (r >= cnt) continue;
                float v0 = acc[mi][ni][2 * h], v1 = acc[mi][ni][2 * h + 1];
                int slot = base + r;
                if (MODE == 0) {
                    *(u32*)(g_htmp + (size_t)slot * IDIM + col) = packh(v0, v1);
                } else if (MODE == 1) {
                    __half2 gh = *(const __half2*)(g_htmp + (size_t)slot * IDIM + col);
                    float gx = __half2float(gh.x), gy = __half2float(gh.y);
                    float ax = gx / (1.f + __expf(-gx)) * v0;
                    float ay = gy / (1.f + __expf(-gy)) * v1;
                    *(u32*)(g_hact + (size_t)slot * IDIM + col) = packh(ax, ay);
                } else {
                    float w = g_sw[slot];
                    float* d = outp + (size_t)g_tok[slot] * H + col;
                    atomicAdd(d, w * v0);
                    atomicAdd(d + 1, w * v1);
                }
            }
        }
    }
}

// ---------------- launch (fork/join; Wu/Wd cvt overlap the GEMMs) ----------
extern "C" void kernel_launch(void* const* d_in, const int* in_sizes, int n_in,
                              void* d_out, int out_size) {
    const float* x     = (const float*)d_in[0];
    const float* Wgate = (const float*)d_in[1];
    const float* Wg    = (const float*)d_in[2];
    const float* Wu    = (const float*)d_in[3];
    const float* Wd    = (const float*)d_in[4];
    float* out = (float*)d_out;

    cudaFuncSetAttribute(gemm_kernel<0>, cudaFuncAttributeMaxDynamicSharedMemorySize, SMEMSZ);
    cudaFuncSetAttribute(gemm_kernel<1>, cudaFuncAttributeMaxDynamicSharedMemorySize, SMEMSZ);
    cudaFuncSetAttribute(gemm_kernel<2>, cudaFuncAttributeMaxDynamicSharedMemorySize, SMEMSZ);
    cudaFuncSetAttribute(router_kernel, cudaFuncAttributeMaxDynamicSharedMemorySize,
                         NE * H * (int)sizeof(float));

    __half *hx, *hwg, *hwu, *hwd, *hact;
    cudaGetSymbolAddress((void**)&hx, g_hx);
    cudaGetSymbolAddress((void**)&hwg, g_hwg);
    cudaGetSymbolAddress((void**)&hwu, g_hwu);
    cudaGetSymbolAddress((void**)&hwd, g_hwd);
    cudaGetSymbolAddress((void**)&hact, g_hact);

    // one-time host-side resources (no device memory involved)
    static cudaStream_t s1 = 0, s2 = 0;
    static cudaEvent_t evF = 0, evG = 0, evU = 0, evD = 0, evR = 0;
    if (!s1) {
        cudaStreamCreateWithFlags(&s1, cudaStreamNonBlocking);
        cudaStreamCreateWithFlags(&s2, cudaStreamNonBlocking);
        cudaEventCreateWithFlags(&evF, cudaEventDisableTiming);
        cudaEventCreateWithFlags(&evG, cudaEventDisableTiming);
        cudaEventCreateWithFlags(&evU, cudaEventDisableTiming);
        cudaEventCreateWithFlags(&evD, cudaEventDisableTiming);
        cudaEventCreateWithFlags(&evR, cudaEventDisableTiming);
    }

    const size_t NW = (size_t)NE * IDIM * H;   // = NE*H*IDIM

    cudaEventRecord(evF, 0);

    // s2: memset + router chain (concurrent with cvt_x/cvt_wg)
    cudaStreamWaitEvent(s2, evF, 0);
    cudaMemsetAsync(out, 0, (size_t)out_size * sizeof(float), s2);
    reset_kernel<<<1, 32, 0, s2>>>();
    router_kernel<<<T / 32, 256, NE * H * sizeof(float), s2>>>(x, Wgate);
    finalize_kernel<<<1, 32, 0, s2>>>(out, out_size);
    assign_kernel<<<(T + 255) / 256, 256, 0, s2>>>();
    cudaEventRecord(evR, s2);

    // default: x + Wg conversions (the only cvt on the critical path)
    cvt16<<<(u32)(((size_t)T * H) / 2048), 256>>>(x, hx, (size_t)T * H);
    cvt16<<<(u32)(NW / 2048), 256>>>(Wg, hwg, NW);
    cudaEventRecord(evG, 0);

    // s1: Wu/Wd conversions run AFTER cvt_wg, overlapping GEMM0/GEMM1
    cudaStreamWaitEvent(s1, evG, 0);
    cvt16<<<(u32)(NW / 2048), 256, 0, s1>>>(Wu, hwu, NW);
    cudaEventRecord(evU, s1);
    cvt16<<<(u32)(NW / 2048), 256, 0, s1>>>(Wd, hwd, NW);
    cudaEventRecord(evD, s1);

    cudaStreamWaitEvent(0, evR, 0);

    dim3 g1(T / BM, IDIM / BN, NE);   // (32, 44, 8)
    gemm_kernel<0><<<g1, 256, SMEMSZ>>>(hx, hwg, out);
    cudaStreamWaitEvent(0, evU, 0);
    gemm_kernel<1><<<g1, 256, SMEMSZ>>>(hx, hwu, out);
    cudaStreamWaitEvent(0, evD, 0);

    dim3 g2(T / BM, H / BN, NE);      // (32, 32, 8)
    gemm_kernel<2><<<g2, 256, SMEMSZ>>>(hact, hwd, out);
}

// round 17
// speedup vs baseline: 1.7623x; 1.0678x over previous
#include <cuda_runtime.h>
#include <cuda_fp16.h>
#include <math.h>

typedef unsigned int u32;

#define H 4096
#define IDIM 5632
#define NE 8
#define T 4096
#define NSLOTS (T * 2)
#define BM 128
#define BN 128
#define BK 64
// stage: A 16KB @0 | B 16KB @16384 => 32KB; 3 stages
#define STAGE 32768
#define SMEMSZ (1024 + 3 * STAGE)

// ---------------- scratch (device globals; allocation-free) ----------------
__device__ __half g_hx[(size_t)T * H];
__device__ __half g_hwg[(size_t)NE * IDIM * H];
__device__ __half g_hwu[(size_t)NE * IDIM * H];
__device__ __half g_hwd[(size_t)NE * H * IDIM];
__device__ __half g_hact[(size_t)NSLOTS * IDIM];   // silu(g)*u, fp16
__device__ __half g_htmp[(size_t)NSLOTS * IDIM];   // raw gate values fp16
__device__ int    g_counts[NE];
__device__ int    g_offsets[NE];
__device__ int    g_cursor[NE];
__device__ int    g_topi[T * 2];
__device__ float  g_topw[T * 2];
__device__ int    g_tok[NSLOTS];
__device__ float  g_sw[NSLOTS];
__device__ float  g_psum[NE];
__device__ float  g_zsum;

// ---------------- helpers ----------------
__device__ __forceinline__ u32 smem_u32(const void* p) {
    u32 a;
    asm("{ .reg .u64 t; cvta.to.shared.u64 t, %1; cvt.u32.u64 %0, t; }" : "=r"(a) : "l"(p));
    return a;
}
// fp16 tile [128 rows][64 cols], 128B rows = 8 chunks of 16B, full XOR swizzle
__device__ __forceinline__ u32 swoff128(int row, int ch) {
    return (u32)(row * 128 + ((ch ^ (row & 7)) << 4));
}
__device__ __forceinline__ u32 packh(float lo, float hi) {
    u32 r;
    asm("cvt.rn.f16x2.f32 %0, %1, %2;" : "=r"(r) : "f"(hi), "f"(lo));
    return r;
}
#define CPASYNC(dst, src) \
    asm volatile("cp.async.cg.shared.global [%0], [%1], 16;" :: "r"(dst), "l"(src) : "memory")
#define CPCOMMIT() asm volatile("cp.async.commit_group;" ::: "memory")
#define CPWAIT1()  asm volatile("cp.async.wait_group 1;" ::: "memory")

#define LDSM4(R, A)                                                             \
    asm volatile("ldmatrix.sync.aligned.m8n8.x4.shared.b16 {%0,%1,%2,%3}, [%4];" \
        : "=r"((R)[0]), "=r"((R)[1]), "=r"((R)[2]), "=r"((R)[3]) : "r"(A))

__device__ __forceinline__ void mma16816(float* d, const u32* a, const u32* b) {
    asm volatile(
        "mma.sync.aligned.m16n8k16.row.col.f32.f16.f16.f32 "
        "{%0,%1,%2,%3},{%4,%5,%6,%7},{%8,%9},{%0,%1,%2,%3};"
        : "+f"(d[0]), "+f"(d[1]), "+f"(d[2]), "+f"(d[3])
        : "r"(a[0]), "r"(a[1]), "r"(a[2]), "r"(a[3]), "r"(b[0]), "r"(b[1]));
}

// ---------------- fp32 -> fp16 conversion pass ----------------
__global__ __launch_bounds__(256)
void cvt16(const float* __restrict__ s, __half* __restrict__ d, size_t n) {
    size_t i = ((size_t)blockIdx.x * 256 + threadIdx.x) * 8;
    if (i >= n) return;
    float4 v0 = *(const float4*)(s + i);
    float4 v1 = *(const float4*)(s + i + 4);
    uint4 o;
    o.x = packh(v0.x, v0.y); o.y = packh(v0.z, v0.w);
    o.z = packh(v1.x, v1.y); o.w = packh(v1.z, v1.w);
    *(uint4*)(d + i) = o;
}

// ---------------- small kernels ----------------
__global__ void reset_kernel() {
    int i = threadIdx.x;
    if (i < NE) { g_counts[i] = 0; g_cursor[i] = 0; g_psum[i] = 0.f; }
    if (i == 0) g_zsum = 0.f;
}

// router: 32 tokens/block, Wgate staged in 128KB smem, warp per 4 tokens
__global__ __launch_bounds__(256)
void router_kernel(const float* __restrict__ x, const float* __restrict__ Wgate) {
    extern __shared__ float swg[];   // NE*H fp32 = 128KB
    for (int i = threadIdx.x; i < NE * H / 4; i += 256)
        ((float4*)swg)[i] = ((const float4*)Wgate)[i];
    __syncthreads();

    int warp = threadIdx.x >> 5, lane = threadIdx.x & 31;
    int t0 = blockIdx.x * 32 + warp * 4;
    const float4* xr = (const float4*)(x + (size_t)t0 * H);
    const float4* wg4 = (const float4*)swg;

    float p[4][NE];
#pragma unroll
    for (int s = 0; s < 4; ++s)
#pragma unroll
        for (int e = 0; e < NE; ++e) p[s][e] = 0.f;

    for (int c = lane; c < H / 4; c += 32) {
        float4 wv[NE];
#pragma unroll
        for (int e = 0; e < NE; ++e) wv[e] = wg4[e * (H / 4) + c];
#pragma unroll
        for (int s = 0; s < 4; ++s) {
            float4 xv = xr[s * (H / 4) + c];
#pragma unroll
            for (int e = 0; e < NE; ++e)
                p[s][e] += xv.x * wv[e].x + xv.y * wv[e].y
                         + xv.z * wv[e].z + xv.w * wv[e].w;
        }
    }
#pragma unroll
    for (int s = 0; s < 4; ++s)
#pragma unroll
        for (int e = 0; e < NE; ++e)
#pragma unroll
            for (int o = 16; o; o >>= 1)
                p[s][e] += __shfl_xor_sync(~0u, p[s][e], o);

    if (lane < 4) {
        int s = lane;
        int t = t0 + s;
        float lg[NE];
#pragma unroll
        for (int e = 0; e < NE; ++e) lg[e] = p[s][e];
        float mx = lg[0];
#pragma unroll
        for (int e = 1; e < NE; ++e) mx = fmaxf(mx, lg[e]);
        float se = 0.f, pr[NE];
#pragma unroll
        for (int e = 0; e < NE; ++e) { pr[e] = expf(lg[e] - mx); se += pr[e]; }
        float inv = 1.f / se;
#pragma unroll
        for (int e = 0; e < NE; ++e) pr[e] *= inv;
        int i0 = 0;
#pragma unroll
        for (int e = 1; e < NE; ++e) if (pr[e] > pr[i0]) i0 = e;
        int i1 = (i0 == 0) ? 1 : 0;
#pragma unroll
        for (int e = 0; e < NE; ++e)
            if (e != i0 && pr[e] > pr[i1]) i1 = e;
        float w0 = pr[i0], w1 = pr[i1];
        float ws = 1.f / (w0 + w1);
        g_topi[2 * t] = i0;     g_topw[2 * t] = w0 * ws;
        g_topi[2 * t + 1] = i1; g_topw[2 * t + 1] = w1 * ws;
        atomicAdd(&g_counts[i0], 1);
        atomicAdd(&g_counts[i1], 1);
#pragma unroll
        for (int e = 0; e < NE; ++e) atomicAdd(&g_psum[e], pr[e]);
        float lse = mx + logf(se);
        atomicAdd(&g_zsum, lse * lse);
    }
}

__global__ void finalize_kernel(float* __restrict__ out, int out_size) {
    if (threadIdx.x == 0 && blockIdx.x == 0) {
        int off = 0;
        for (int e = 0; e < NE; ++e) { g_offsets[e] = off; g_cursor[e] = off; off += g_counts[e]; }
        float aux = 0.f;
        for (int e = 0; e < NE; ++e)
            aux += (g_psum[e] / (float)T) * ((float)g_counts[e] / (float)(T * 2));
        aux *= (float)NE;
        float z = g_zsum / (float)T;
        if (out_size > T * H) out[(size_t)T * H] = 0.02f * aux + 0.001f * z;
    }
}

__global__ void assign_kernel() {
    int t = blockIdx.x * blockDim.x + threadIdx.x;
    if (t >= T) return;
#pragma unroll
    for (int k = 0; k < 2; ++k) {
        int e = g_topi[2 * t + k];
        int s = atomicAdd(&g_cursor[e], 1);
        g_tok[s] = t;
        g_sw[s] = g_topw[2 * t + k];
    }
}

// ---------------- fp16 MMA GEMM, cp.async 3-stage; per-expert launch -------
// MODE 0: A=hx(gather), B=hwg -> g_htmp (raw gate, fp16)
// MODE 1: A=hx(gather), B=hwu -> g_hact = silu(g_htmp)*u (fp16)
// MODE 2: A=g_hact,     B=hwd -> out[tok] += w * result (atomic fp32)
template <int MODE>
__global__ __launch_bounds__(256, 2)
void gemm_kernel(const __half* __restrict__ Asrc, const __half* __restrict__ W,
                 float* __restrict__ outp, int e) {
    constexpr int KD = (MODE == 2) ? IDIM : H;
    constexpr int KT = KD / BK;

    int cnt = g_counts[e];
    int m0 = blockIdx.x * BM;
    if (m0 >= cnt) return;
    int base = g_offsets[e];
    int n0 = blockIdx.y * BN;

    extern __shared__ char smem[];
    const __half** aptr = (const __half**)smem;   // 128 row pointers (1 KB)
    u32 tiles = smem_u32(smem) + 1024;            // 3 stages x 32 KB

    int tid = threadIdx.x, lane = tid & 31, wid = tid >> 5;
    int wm = wid & 3, wn = wid >> 2;

    if (tid < 128) {
        int r = m0 + tid;
        int slot = base + ((r < cnt) ? r : (cnt - 1));
        aptr[tid] = (MODE == 2) ? (Asrc + (size_t)slot * IDIM)
                                : (Asrc + (size_t)g_tok[slot] * H);
    }
    __syncthreads();

    const __half* wB = W + (size_t)e * ((size_t)IDIM * H) + (size_t)n0 * KD;

    // loader: each thread copies 4 A chunks + 4 B chunks (16B each) per stage
    int lrow = tid >> 1, lch = (tid & 1) * 4;
    const __half* aRow = aptr[lrow] + lch * 8;
    const __half* bRow = wB + (size_t)lrow * KD + lch * 8;
    u32 so0 = swoff128(lrow, lch),     so1 = swoff128(lrow, lch + 1);
    u32 so2 = swoff128(lrow, lch + 2), so3 = swoff128(lrow, lch + 3);

#define ISSUE(sb, k0) do {                                  \
    u32 _s = (sb); int _k = (k0);                           \
    CPASYNC(_s + so0,         aRow + _k);                   \
    CPASYNC(_s + so1,         aRow + _k + 8);               \
    CPASYNC(_s + so2,         aRow + _k + 16);              \
    CPASYNC(_s + so3,         aRow + _k + 24);              \
    CPASYNC(_s + 16384 + so0, bRow + _k);                   \
    CPASYNC(_s + 16384 + so1, bRow + _k + 8);               \
    CPASYNC(_s + 16384 + so2, bRow + _k + 16);              \
    CPASYNC(_s + 16384 + so3, bRow + _k + 24);              \
} while (0)

    // prologue: stages 0 and 1
    ISSUE(tiles, 0);
    CPCOMMIT();
    ISSUE(tiles + STAGE, BK);
    CPCOMMIT();

    float acc[2][8][4];
#pragma unroll
    for (int i = 0; i < 2; ++i)
#pragma unroll
        for (int j = 0; j < 8; ++j)
#pragma unroll
            for (int c = 0; c < 4; ++c) acc[i][j][c] = 0.f;

#pragma unroll 1
    for (int kt = 0; kt < KT; ++kt) {
        CPWAIT1();
        __syncthreads();
        if (kt + 2 < KT) {
            int nslot = (kt + 2) % 3;
            ISSUE(tiles + nslot * STAGE, (kt + 2) * BK);
        }
        CPCOMMIT();

        u32 stage = tiles + (kt % 3) * STAGE;
#pragma unroll
        for (int ks = 0; ks < 4; ++ks) {
            u32 Ah[2][4];
#pragma unroll
            for (int mi = 0; mi < 2; ++mi) {
                int row = wm * 32 + mi * 16 + (lane & 15);
                int ch = ks * 2 + (lane >> 4);
                LDSM4(Ah[mi], stage + swoff128(row, ch));
            }
#pragma unroll
            for (int p = 0; p < 4; ++p) {
                int row = wn * 64 + p * 16 + ((lane >> 4) << 3) + (lane & 7);
                int ch = ks * 2 + ((lane >> 3) & 1);
                u32 Bh[4];
                LDSM4(Bh, stage + 16384 + swoff128(row, ch));
#pragma unroll
                for (int mi = 0; mi < 2; ++mi) {
                    mma16816(acc[mi][2 * p],     Ah[mi], Bh);
                    mma16816(acc[mi][2 * p + 1], Ah[mi], Bh + 2);
                }
            }
        }
    }
#undef ISSUE

    // epilogue
    int rA = m0 + wm * 32 + (lane >> 2);
    int cA = n0 + wn * 64 + (lane & 3) * 2;
#pragma unroll
    for (int mi = 0; mi < 2; ++mi) {
#pragma unroll
        for (int ni = 0; ni < 8; ++ni) {
            int col = cA + ni * 8;
#pragma unroll
            for (int h = 0; h < 2; ++h) {
                int r = rA + mi * 16 + h * 8;
                if (r >= cnt) continue;
                float v0 = acc[mi][ni][2 * h], v1 = acc[mi][ni][2 * h + 1];
                int slot = base + r;
                if (MODE == 0) {
                    *(u32*)(g_htmp + (size_t)slot * IDIM + col) = packh(v0, v1);
                } else if (MODE == 1) {
                    __half2 gh = *(const __half2*)(g_htmp + (size_t)slot * IDIM + col);
                    float gx = __half2float(gh.x), gy = __half2float(gh.y);
                    float ax = gx / (1.f + __expf(-gx)) * v0;
                    float ay = gy / (1.f + __expf(-gy)) * v1;
                    *(u32*)(g_hact + (size_t)slot * IDIM + col) = packh(ax, ay);
                } else {
                    float w = g_sw[slot];
                    float* d = outp + (size_t)g_tok[slot] * H + col;
                    atomicAdd(d, w * v0);
                    atomicAdd(d + 1, w * v1);
                }
            }
        }
    }
}

// ---------------- launch: per-expert pipelining, 2 streams + 5 events ------
extern "C" void kernel_launch(void* const* d_in, const int* in_sizes, int n_in,
                              void* d_out, int out_size) {
    const float* x     = (const float*)d_in[0];
    const float* Wgate = (const float*)d_in[1];
    const float* Wg    = (const float*)d_in[2];
    const float* Wu    = (const float*)d_in[3];
    const float* Wd    = (const float*)d_in[4];
    float* out = (float*)d_out;

    cudaFuncSetAttribute(gemm_kernel<0>, cudaFuncAttributeMaxDynamicSharedMemorySize, SMEMSZ);
    cudaFuncSetAttribute(gemm_kernel<1>, cudaFuncAttributeMaxDynamicSharedMemorySize, SMEMSZ);
    cudaFuncSetAttribute(gemm_kernel<2>, cudaFuncAttributeMaxDynamicSharedMemorySize, SMEMSZ);
    cudaFuncSetAttribute(router_kernel, cudaFuncAttributeMaxDynamicSharedMemorySize,
                         NE * H * (int)sizeof(float));

    __half *hx, *hwg, *hwu, *hwd, *hact;
    cudaGetSymbolAddress((void**)&hx, g_hx);
    cudaGetSymbolAddress((void**)&hwg, g_hwg);
    cudaGetSymbolAddress((void**)&hwu, g_hwu);
    cudaGetSymbolAddress((void**)&hwd, g_hwd);
    cudaGetSymbolAddress((void**)&hact, g_hact);

    // one-time host-side resources: 2 streams + 5 events (same as passing R15)
    static cudaStream_t s1 = 0, s2 = 0;
    static cudaEvent_t evF = 0, evX = 0, evR = 0, evW = 0, evJ = 0;
    if (!s1) {
        cudaStreamCreateWithFlags(&s1, cudaStreamNonBlocking);
        cudaStreamCreateWithFlags(&s2, cudaStreamNonBlocking);
        cudaEventCreateWithFlags(&evF, cudaEventDisableTiming);
        cudaEventCreateWithFlags(&evX, cudaEventDisableTiming);
        cudaEventCreateWithFlags(&evR, cudaEventDisableTiming);
        cudaEventCreateWithFlags(&evW, cudaEventDisableTiming);
        cudaEventCreateWithFlags(&evJ, cudaEventDisableTiming);
    }

    const size_t WSZ = (size_t)IDIM * H;   // per-expert weight elements
    const u32 cvtb = (u32)(WSZ / 2048);
    dim3 g01(T / BM, IDIM / BN, 1);   // (32, 44)
    dim3 g2d(T / BM, H / BN, 1);      // (32, 32)

    cudaEventRecord(evF, 0);

    // s2: memset + router chain, then hosts odd-expert GEMMs
    cudaStreamWaitEvent(s2, evF, 0);
    cudaMemsetAsync(out, 0, (size_t)out_size * sizeof(float), s2);
    reset_kernel<<<1, 32, 0, s2>>>();
    router_kernel<<<T / 32, 256, NE * H * sizeof(float), s2>>>(x, Wgate);
    finalize_kernel<<<1, 32, 0, s2>>>(out, out_size);
    assign_kernel<<<(T + 255) / 256, 256, 0, s2>>>();
    cudaEventRecord(evR, s2);

    // s1: x conversion, then per-expert weight slices
    cudaStreamWaitEvent(s1, evF, 0);
    cvt16<<<(u32)(((size_t)T * H) / 2048), 256, 0, s1>>>(x, hx, (size_t)T * H);
    cudaEventRecord(evX, s1);

    // GEMM host streams: default (even experts), s2 (odd experts)
    cudaStreamWaitEvent(0, evX, 0);
    cudaStreamWaitEvent(0, evR, 0);
    cudaStreamWaitEvent(s2, evX, 0);   // s2 already ordered after its own router chain

    // GEMM0 per expert, gated on its own cvt_wg slice (evW reused; wait binds
    // to the most recent record at host issue time)
    for (int e = 0; e < NE; ++e) {
        size_t off = (size_t)e * WSZ;
        cudaStream_t tgt = (e & 1) ? s2 : (cudaStream_t)0;
        cvt16<<<cvtb, 256, 0, s1>>>(Wg + off, hwg + off, WSZ);
        cudaEventRecord(evW, s1);
        cudaStreamWaitEvent(tgt, evW, 0);
        gemm_kernel<0><<<g01, 256, SMEMSZ, tgt>>>(hx, hwg, out, e);
    }
    // GEMM1 per expert (after gemm0(e) by stream order, after cvt_wu(e) by evW)
    for (int e = 0; e < NE; ++e) {
        size_t off = (size_t)e * WSZ;
        cudaStream_t tgt = (e & 1) ? s2 : (cudaStream_t)0;
        cvt16<<<cvtb, 256, 0, s1>>>(Wu + off, hwu + off, WSZ);
        cudaEventRecord(evW, s1);
        cudaStreamWaitEvent(tgt, evW, 0);
        gemm_kernel<1><<<g01, 256, SMEMSZ, tgt>>>(hx, hwu, out, e);
    }
    // GEMM2 per expert
    for (int e = 0; e < NE; ++e) {
        size_t off = (size_t)e * WSZ;
        cudaStream_t tgt = (e & 1) ? s2 : (cudaStream_t)0;
        cvt16<<<cvtb, 256, 0, s1>>>(Wd + off, hwd + off, WSZ);
        cudaEventRecord(evW, s1);
        cudaStreamWaitEvent(tgt, evW, 0);
        gemm_kernel<2><<<g2d, 256, SMEMSZ, tgt>>>(hact, hwd, out, e);
    }

    // join s2 back into the capture (default) stream
    cudaEventRecord(evJ, s2);
    cudaStreamWaitEvent(0, evJ, 0);
}